// round 1
// baseline (speedup 1.0000x reference)
#include <cuda_runtime.h>

#define HW     9216
#define IMG_W  96
#define IMG_H  96
#define CCH    192
#define NB     4

// Scratch (no cudaMalloc allowed): qkv = [B][576][H][W], attn = [B][192][H][W]
__device__ float g_qkv[NB * 3 * CCH * HW];
__device__ float g_attn[NB * CCH * HW];

// ----------------------------------------------------------------------------
// fp32 GEMM: C[m,n] = sum_k A[m,k] * B[k,n]
// A row-major [M x K] (lda=K), B row-major [K x N] (ldb=N), C row-major (ldc=N)
// blockIdx.z selects batch via strideB/strideC. Dims must divide tiles:
//   qkv:  M=576, N=9216, K=192   out: M=192, N=9216, K=192   (all divide)
// BM=64, BN=128, BK=16, 256 threads, 4x8 microtile, double-buffered smem.
// ----------------------------------------------------------------------------
template<int BM, int BN, int BK>
__global__ __launch_bounds__(256, 2)
void gemm_kernel(const float* __restrict__ A, const float* __restrict__ B,
                 float* __restrict__ C, int M, int N, int K,
                 int strideB, int strideC)
{
    __shared__ float As[2][BK][BM + 4];   // transposed A tile, padded
    __shared__ float Bs[2][BK][BN];

    const float* Bb = B + (size_t)blockIdx.z * (size_t)strideB;
    float*       Cb = C + (size_t)blockIdx.z * (size_t)strideC;

    const int m0 = blockIdx.y * BM;
    const int n0 = blockIdx.x * BN;
    const int t  = threadIdx.x;
    const int ty = t >> 4;        // 0..15 -> rows (x4)
    const int tx = t & 15;        // 0..15 -> cols (x4, two 64-wide halves)

    // loader indices
    const int am = t >> 2;            // 0..63  A row within tile
    const int ak = (t & 3) * 4;       // 0,4,8,12
    const int bk = t >> 5;            // 0..7   B k-row
    const int bn = (t & 31) * 4;      // 0..124

    float acc[4][8];
    #pragma unroll
    for (int i = 0; i < 4; i++)
        #pragma unroll
        for (int j = 0; j < 8; j++) acc[i][j] = 0.f;

    const int nk = K / BK;

    // preload tile 0
    {
        float4 a = *(const float4*)&A[(m0 + am) * K + ak];
        As[0][ak + 0][am] = a.x; As[0][ak + 1][am] = a.y;
        As[0][ak + 2][am] = a.z; As[0][ak + 3][am] = a.w;
        float4 v0 = *(const float4*)&Bb[(size_t)bk       * N + n0 + bn];
        float4 v1 = *(const float4*)&Bb[(size_t)(bk + 8) * N + n0 + bn];
        *(float4*)&Bs[0][bk][bn]     = v0;
        *(float4*)&Bs[0][bk + 8][bn] = v1;
    }
    __syncthreads();

    for (int kt = 0; kt < nk; kt++) {
        const int cur = kt & 1;
        float4 pa, pb0, pb1;
        if (kt + 1 < nk) {
            const int kbse = (kt + 1) * BK;
            pa  = *(const float4*)&A[(m0 + am) * K + kbse + ak];
            pb0 = *(const float4*)&Bb[(size_t)(kbse + bk)     * N + n0 + bn];
            pb1 = *(const float4*)&Bb[(size_t)(kbse + bk + 8) * N + n0 + bn];
        }
        #pragma unroll
        for (int kk = 0; kk < BK; kk++) {
            float4 av  = *(const float4*)&As[cur][kk][ty * 4];
            float4 bv0 = *(const float4*)&Bs[cur][kk][tx * 4];
            float4 bv1 = *(const float4*)&Bs[cur][kk][64 + tx * 4];
            float ar[4] = {av.x, av.y, av.z, av.w};
            float br[8] = {bv0.x, bv0.y, bv0.z, bv0.w,
                           bv1.x, bv1.y, bv1.z, bv1.w};
            #pragma unroll
            for (int i = 0; i < 4; i++)
                #pragma unroll
                for (int j = 0; j < 8; j++)
                    acc[i][j] += ar[i] * br[j];
        }
        if (kt + 1 < nk) {
            const int nxt = cur ^ 1;
            As[nxt][ak + 0][am] = pa.x; As[nxt][ak + 1][am] = pa.y;
            As[nxt][ak + 2][am] = pa.z; As[nxt][ak + 3][am] = pa.w;
            *(float4*)&Bs[nxt][bk][bn]     = pb0;
            *(float4*)&Bs[nxt][bk + 8][bn] = pb1;
        }
        __syncthreads();
    }

    #pragma unroll
    for (int i = 0; i < 4; i++) {
        const int row = m0 + ty * 4 + i;
        float4 v0 = make_float4(acc[i][0], acc[i][1], acc[i][2], acc[i][3]);
        float4 v1 = make_float4(acc[i][4], acc[i][5], acc[i][6], acc[i][7]);
        *(float4*)&Cb[(size_t)row * N + n0 + tx * 4]      = v0;
        *(float4*)&Cb[(size_t)row * N + n0 + 64 + tx * 4] = v1;
    }
}

// ----------------------------------------------------------------------------
// Neighborhood attention, one thread per pixel, q/out in registers.
// Layout of g_qkv: [b][576][HW] with q = ch 0..191, k = 192..383, v = 384..575,
// head i owns ch i*32..i*32+31 within each group (d-major -> coalesced loads).
// Single-pass softmax (scores tiny, |arg| < 1, identical math to ref).
// OOB neighbors: score = bias only (zero-padded k), v contributes 0 —
// still counted in the denominator, matching the reference unfold semantics.
// ----------------------------------------------------------------------------
template<int K, int DIL>
__device__ __forceinline__ void natt_body(const float* __restrict__ bias,
                                          int head, int b)
{
    const int w   = blockIdx.x * 32 + threadIdx.x;
    const int h   = blockIdx.y * 4  + threadIdx.y;
    const int pix = h * IMG_W + w;

    const float* qb = g_qkv + ((size_t)b * 576 + head * 32) * HW;
    const float* kb = qb + (size_t)CCH * HW;
    const float* vb = qb + (size_t)2 * CCH * HW;

    float q[32];
    #pragma unroll
    for (int d = 0; d < 32; d++) q[d] = qb[d * HW + pix];

    float out[32];
    #pragma unroll
    for (int d = 0; d < 32; d++) out[d] = 0.f;
    float l = 0.f;
    const float scale = 0.17677669529663689f;   // 1/sqrt(32)

    #pragma unroll 1
    for (int di = 0; di < K; di++) {
        const int hh  = h + (di - K / 2) * DIL;
        const bool rok = ((unsigned)hh < IMG_H);
        #pragma unroll
        for (int dj = 0; dj < K; dj++) {
            const int ww  = w + (dj - K / 2) * DIL;
            const bool ok = rok && ((unsigned)ww < IMG_W);
            const int off = hh * IMG_W + ww;
            float s = 0.f;
            if (ok) {
                #pragma unroll
                for (int d = 0; d < 32; d++)
                    s += q[d] * __ldg(&kb[d * HW + off]);
            }
            const float e = __expf(s * scale + __ldg(&bias[di * K + dj]));
            l += e;
            if (ok) {
                #pragma unroll
                for (int d = 0; d < 32; d++)
                    out[d] += e * __ldg(&vb[d * HW + off]);
            }
        }
    }

    const float il = 1.f / l;
    float* op = g_attn + ((size_t)b * CCH + head * 32) * HW + pix;
    #pragma unroll
    for (int d = 0; d < 32; d++) op[d * HW] = out[d] * il;
}

__global__ __launch_bounds__(128)
void natt_all(const float* __restrict__ b0, const float* __restrict__ b1,
              const float* __restrict__ b2, const float* __restrict__ b3,
              const float* __restrict__ b4, const float* __restrict__ b5)
{
    const int z    = blockIdx.z;
    const int head = z % 6;
    const int b    = z / 6;
    switch (head) {
        case 0: natt_body<3, 1>(b0, 0, b); break;
        case 1: natt_body<5, 2>(b1, 1, b); break;
        case 2: natt_body<7, 1>(b2, 2, b); break;
        case 3: natt_body<7, 3>(b3, 3, b); break;
        case 4: natt_body<9, 1>(b4, 4, b); break;
        case 5: natt_body<9, 2>(b5, 5, b); break;
    }
}

// ----------------------------------------------------------------------------
// Launch: qkv GEMM -> fused-per-head attention -> output GEMM
// ----------------------------------------------------------------------------
extern "C" void kernel_launch(void* const* d_in, const int* in_sizes, int n_in,
                              void* d_out, int out_size)
{
    (void)in_sizes; (void)n_in; (void)out_size;
    const float* x     = (const float*)d_in[0];
    const float* w_qkv = (const float*)d_in[1];
    const float* w_out = (const float*)d_in[2];
    const float* b0 = (const float*)d_in[3];
    const float* b1 = (const float*)d_in[4];
    const float* b2 = (const float*)d_in[5];
    const float* b3 = (const float*)d_in[6];
    const float* b4 = (const float*)d_in[7];
    const float* b5 = (const float*)d_in[8];

    float* qkv  = nullptr;
    float* attn = nullptr;
    cudaGetSymbolAddress((void**)&qkv,  g_qkv);
    cudaGetSymbolAddress((void**)&attn, g_attn);

    // QKV projection: per batch [576 x 9216] = w_qkv[576x192] @ x_b[192x9216]
    gemm_kernel<64, 128, 16><<<dim3(HW / 128, 576 / 64, NB), 256>>>(
        w_qkv, x, qkv, 576, HW, CCH, CCH * HW, 3 * CCH * HW);

    // Neighborhood attention, all (batch, head) pairs in one grid
    natt_all<<<dim3(IMG_W / 32, IMG_H / 4, NB * 6), dim3(32, 4)>>>(
        b0, b1, b2, b3, b4, b5);

    // Output projection: per batch [192 x 9216] = w_out[192x192] @ attn_b[192x9216]
    gemm_kernel<64, 128, 16><<<dim3(HW / 128, CCH / 64, NB), 256>>>(
        w_out, attn, (float*)d_out, CCH, HW, CCH, CCH * HW, CCH * HW);
}